// round 11
// baseline (speedup 1.0000x reference)
#include <cuda_runtime.h>
#include <cuda_bf16.h>
#include <cstdint>
#include <math.h>
#include <math_constants.h>

// Problem constants
#define BB 32
#define SS 512
#define DD 256
#define HH 8
#define DHH 32
#define NROWS (BB*SS)

// Scratch (__device__ globals; allocation is banned)
__device__ float g_qkv[(size_t)NROWS * 768];   // [row][0:256)=q, [256:512)=k, [512:768)=v
__device__ float g_tmp[(size_t)NROWS * 256];   // avg @ v result

// ---------------------------------------------------------------------------
// bf16 split + pack helpers (3xBF16 fp32 emulation)
// ---------------------------------------------------------------------------
__device__ __forceinline__ void splitpk(float x, float y, uint32_t& h, uint32_t& l) {
    __nv_bfloat16 hx = __float2bfloat16(x), hy = __float2bfloat16(y);
    float rx = x - __bfloat162float(hx);
    float ry = y - __bfloat162float(hy);
    __nv_bfloat16 lx = __float2bfloat16(rx), ly = __float2bfloat16(ry);
    h = (uint32_t)__bfloat16_as_ushort(hx) | ((uint32_t)__bfloat16_as_ushort(hy) << 16);
    l = (uint32_t)__bfloat16_as_ushort(lx) | ((uint32_t)__bfloat16_as_ushort(ly) << 16);
}

__device__ __forceinline__ uint32_t cvta_s(const void* p) {
    return (uint32_t)__cvta_generic_to_shared(p);
}

__device__ __forceinline__ void ldmx4(uint32_t r[4], uint32_t addr) {
    asm volatile("ldmatrix.sync.aligned.m8n8.x4.shared.b16 {%0,%1,%2,%3}, [%4];"
                 : "=r"(r[0]), "=r"(r[1]), "=r"(r[2]), "=r"(r[3]) : "r"(addr));
}
__device__ __forceinline__ void ldmx4t(uint32_t r[4], uint32_t addr) {
    asm volatile("ldmatrix.sync.aligned.m8n8.x4.trans.shared.b16 {%0,%1,%2,%3}, [%4];"
                 : "=r"(r[0]), "=r"(r[1]), "=r"(r[2]), "=r"(r[3]) : "r"(addr));
}

__device__ __forceinline__ void mma16816(float c[4], const uint32_t a[4],
                                         uint32_t b0, uint32_t b1) {
    asm volatile(
        "mma.sync.aligned.m16n8k16.row.col.f32.bf16.bf16.f32 "
        "{%0,%1,%2,%3}, {%4,%5,%6,%7}, {%8,%9}, {%0,%1,%2,%3};"
        : "+f"(c[0]), "+f"(c[1]), "+f"(c[2]), "+f"(c[3])
        : "r"(a[0]), "r"(a[1]), "r"(a[2]), "r"(a[3]), "r"(b0), "r"(b1));
}

// ---------------------------------------------------------------------------
// Tile strides
// ---------------------------------------------------------------------------
#define AT_STR 40    // K-major tiles: 32 k + 8 pad
#define BN_STR 136   // NN B tile [k][n]: 128 n + 8 pad

// Byte sizes / offsets for the double-buffered GEMM smem
#define TN_TILE_B  (128 * AT_STR * 2)            // 10240
#define TN_BUF_B   (4 * TN_TILE_B)               // Ahi,Alo,Bhi,Blo = 40960
#define TN_SMEM_B  (2 * TN_BUF_B)                // 81920

#define NN_BT_B    (32 * BN_STR * 2)             // 8704
#define NN_BUF_B   (2 * TN_TILE_B + 2 * NN_BT_B) // 37888
#define NN_SMEM_B  (2 * NN_BUF_B)                // 75776

// Stage a 128x32 fp32 K-contig tile -> hi/lo bf16 smem (row stride AT_STR)
__device__ __forceinline__ void stage_tn(uint16_t* hi, uint16_t* lo,
                                         const float4 f[4], int tid) {
    int row = tid >> 1, kh = (tid & 1) * 16;
    uint4 H0, H1, L0, L1;
    splitpk(f[0].x, f[0].y, H0.x, L0.x); splitpk(f[0].z, f[0].w, H0.y, L0.y);
    splitpk(f[1].x, f[1].y, H0.z, L0.z); splitpk(f[1].z, f[1].w, H0.w, L0.w);
    splitpk(f[2].x, f[2].y, H1.x, L1.x); splitpk(f[2].z, f[2].w, H1.y, L1.y);
    splitpk(f[3].x, f[3].y, H1.z, L1.z); splitpk(f[3].z, f[3].w, H1.w, L1.w);
    *(uint4*)(hi + row * AT_STR + kh)     = H0;
    *(uint4*)(hi + row * AT_STR + kh + 8) = H1;
    *(uint4*)(lo + row * AT_STR + kh)     = L0;
    *(uint4*)(lo + row * AT_STR + kh + 8) = L1;
}

// Stage a 32x128 fp32 N-contig tile -> hi/lo bf16 smem [k][n] (stride BN_STR)
__device__ __forceinline__ void stage_nn_b(uint16_t* hi, uint16_t* lo,
                                           const float4 f[4], int tid) {
    int k = tid >> 3, nq = (tid & 7) * 16;
    uint4 H0, H1, L0, L1;
    splitpk(f[0].x, f[0].y, H0.x, L0.x); splitpk(f[0].z, f[0].w, H0.y, L0.y);
    splitpk(f[1].x, f[1].y, H0.z, L0.z); splitpk(f[1].z, f[1].w, H0.w, L0.w);
    splitpk(f[2].x, f[2].y, H1.x, L1.x); splitpk(f[2].z, f[2].w, H1.y, L1.y);
    splitpk(f[3].x, f[3].y, H1.z, L1.z); splitpk(f[3].z, f[3].w, H1.w, L1.w);
    *(uint4*)(hi + k * BN_STR + nq)     = H0;
    *(uint4*)(hi + k * BN_STR + nq + 8) = H1;
    *(uint4*)(lo + k * BN_STR + nq)     = L0;
    *(uint4*)(lo + k * BN_STR + nq + 8) = L1;
}

template<bool TRANSB>
__device__ __forceinline__ void compute_chunk(
    float c[4][4][4],
    const uint16_t* sAhi, const uint16_t* sAlo,
    const uint16_t* sBhi, const uint16_t* sBlo,
    int lane, int mrow0, int ncol0)
{
    const int lr = lane & 7, lg = lane >> 3;
#pragma unroll
    for (int k16 = 0; k16 < 32; k16 += 16) {
        uint32_t ah[4][4], al[4][4];
        uint32_t aoff = (uint32_t)(((mrow0 + (lane & 15)) * AT_STR + k16 + ((lane >> 4) << 3)) * 2);
#pragma unroll
        for (int mi = 0; mi < 4; ++mi) {
            ldmx4(ah[mi], cvta_s(sAhi) + aoff + mi * (16 * AT_STR * 2));
            ldmx4(al[mi], cvta_s(sAlo) + aoff + mi * (16 * AT_STR * 2));
        }
        uint32_t bh[2][4], bl[2][4];
#pragma unroll
        for (int nb = 0; nb < 2; ++nb) {
            uint32_t boff;
            if (TRANSB) {
                boff = (uint32_t)(((k16 + lr + ((lg & 1) << 3)) * BN_STR
                                   + ncol0 + nb * 16 + ((lg & 2) << 2)) * 2);
                ldmx4t(bh[nb], cvta_s(sBhi) + boff);
                ldmx4t(bl[nb], cvta_s(sBlo) + boff);
            } else {
                boff = (uint32_t)(((ncol0 + nb * 16 + lr + ((lg & 2) << 2)) * AT_STR
                                   + k16 + ((lg & 1) << 3)) * 2);
                ldmx4(bh[nb], cvta_s(sBhi) + boff);
                ldmx4(bl[nb], cvta_s(sBlo) + boff);
            }
        }
#pragma unroll
        for (int mi = 0; mi < 4; ++mi)
#pragma unroll
            for (int nb = 0; nb < 2; ++nb)
#pragma unroll
                for (int half = 0; half < 2; ++half) {
                    float* cc = c[mi][nb * 2 + half];
                    mma16816(cc, ah[mi], bh[nb][half * 2], bh[nb][half * 2 + 1]);
                    mma16816(cc, ah[mi], bl[nb][half * 2], bl[nb][half * 2 + 1]);
                    mma16816(cc, al[mi], bh[nb][half * 2], bh[nb][half * 2 + 1]);
                }
    }
}

__device__ __forceinline__ void epilogue_store(
    float c[4][4][4], float* __restrict__ C, const float* __restrict__ bias,
    int ldc, int m0, int cn0, int mrow0, int ncol0, int lane)
{
#pragma unroll
    for (int mi = 0; mi < 4; ++mi) {
        int r = m0 + mrow0 + mi * 16 + (lane >> 2);
#pragma unroll
        for (int ni = 0; ni < 4; ++ni) {
            int cl = ncol0 + ni * 8 + ((lane & 3) << 1);
            float b0 = 0.f, b1 = 0.f;
            if (bias) { b0 = bias[cl]; b1 = bias[cl + 1]; }
            float2 v0 = make_float2(c[mi][ni][0] + b0, c[mi][ni][1] + b1);
            float2 v1 = make_float2(c[mi][ni][2] + b0, c[mi][ni][3] + b1);
            *(float2*)(C + (size_t)r * ldc + cn0 + cl) = v0;
            *(float2*)(C + (size_t)(r + 8) * ldc + cn0 + cl) = v1;
        }
    }
}

// ---------------------------------------------------------------------------
// TN GEMM body — double-buffered pipeline: LDG prefetch -> compute(cur) ->
// stage(next) -> one sync per chunk.
// ---------------------------------------------------------------------------
__device__ __forceinline__ void gemm_tn_mma_body(
    char* sm,
    const float* __restrict__ A, const float* __restrict__ B,
    const float* __restrict__ bias, float* __restrict__ C,
    int K, int lda, int ldb, int ldc, int m0, int cn0)
{
    const int tid = threadIdx.x;
    const int lane = tid & 31, warp = tid >> 5;
    const int mrow0 = (warp & 1) * 64, ncol0 = (warp >> 1) * 32;
    const int row = tid >> 1, kh = (tid & 1) * 16;

    float c[4][4][4];
#pragma unroll
    for (int i = 0; i < 4; ++i)
#pragma unroll
        for (int j = 0; j < 4; ++j)
#pragma unroll
            for (int q = 0; q < 4; ++q) c[i][j][q] = 0.f;

    const float* pA = A + (size_t)(m0 + row) * lda + kh;
    const float* pB = B + (size_t)row * ldb + kh;

    float4 fa[4], fb[4];
#pragma unroll
    for (int i = 0; i < 4; ++i) {
        fa[i] = *(const float4*)(pA + i * 4);
        fb[i] = *(const float4*)(pB + i * 4);
    }
    {
        uint16_t* b0 = (uint16_t*)sm;
        stage_tn(b0,                 b0 + TN_TILE_B / 2,     fa, tid);
        stage_tn(b0 + TN_TILE_B,     b0 + 3 * TN_TILE_B / 2, fb, tid);
    }
    __syncthreads();

    int ib = 0;
    for (int k0 = 0; k0 < K; k0 += 32, ib ^= 1) {
        const bool has_next = (k0 + 32 < K);
        if (has_next) {
#pragma unroll
            for (int i = 0; i < 4; ++i) {
                fa[i] = *(const float4*)(pA + k0 + 32 + i * 4);
                fb[i] = *(const float4*)(pB + k0 + 32 + i * 4);
            }
        }
        uint16_t* cur = (uint16_t*)(sm + ib * TN_BUF_B);
        compute_chunk<false>(c, cur, cur + TN_TILE_B / 2,
                             cur + TN_TILE_B, cur + 3 * TN_TILE_B / 2,
                             lane, mrow0, ncol0);
        if (has_next) {
            uint16_t* nxt = (uint16_t*)(sm + (ib ^ 1) * TN_BUF_B);
            stage_tn(nxt,                 nxt + TN_TILE_B / 2,     fa, tid);
            stage_tn(nxt + TN_TILE_B,     nxt + 3 * TN_TILE_B / 2, fb, tid);
        }
        __syncthreads();
    }
    epilogue_store(c, C, bias, ldc, m0, cn0, mrow0, ncol0, lane);
}

__global__ __launch_bounds__(256) void mma_qkv(
    const float* __restrict__ x,
    const float* __restrict__ Wq, const float* __restrict__ bq,
    const float* __restrict__ Wk, const float* __restrict__ bk,
    const float* __restrict__ Wv, const float* __restrict__ bv,
    float* __restrict__ qkv)
{
    extern __shared__ __align__(16) char sm[];
    const int z = blockIdx.x;
    const int m0 = blockIdx.y * 128;
    const float* B; const float* bias;
    if (z < 2)      { B = Wq + (size_t)z * 128 * 256;       bias = bq + z * 128; }
    else if (z < 4) { B = Wk + (size_t)(z - 2) * 128 * 256; bias = bk + (z - 2) * 128; }
    else            { B = Wv + (size_t)(z - 4) * 128 * 256; bias = bv + (z - 4) * 128; }
    gemm_tn_mma_body(sm, x, B, bias, qkv, 256, 256, 256, 768, m0, z * 128);
}

__global__ __launch_bounds__(256) void mma_out(
    const float* __restrict__ tmp, const float* __restrict__ Wo,
    const float* __restrict__ bo, float* __restrict__ out)
{
    extern __shared__ __align__(16) char sm[];
    const int n0 = blockIdx.x * 128;
    const int m0 = blockIdx.y * 128;
    gemm_tn_mma_body(sm, tmp, Wo + (size_t)n0 * 256, bo + n0, out,
                     256, 256, 256, 256, m0, n0);
}

// ---------------------------------------------------------------------------
// NN batched (double-buffered): tmp[b] = avg[b] @ v[b]
// Buffer layout per buf: Ahi, Alo (128xAT_STR), Bhi, Blo (32xBN_STR)
// ---------------------------------------------------------------------------
__global__ __launch_bounds__(256) void mma_nn(
    const float* __restrict__ avg, const float* __restrict__ qkv,
    float* __restrict__ tmp)
{
    extern __shared__ __align__(16) char sm[];
    const int tid = threadIdx.x;
    const int lane = tid & 31, warp = tid >> 5;
    const int mrow0 = (warp & 1) * 64, ncol0 = (warp >> 1) * 32;
    const int n0 = blockIdx.x * 128;
    const int m0 = blockIdx.y * 128;
    const int b  = blockIdx.z;

    const float* A = avg + (size_t)b * 512 * 512;
    const float* B = qkv + (size_t)b * 512 * 768 + 512;

    float c[4][4][4];
#pragma unroll
    for (int i = 0; i < 4; ++i)
#pragma unroll
        for (int j = 0; j < 4; ++j)
#pragma unroll
            for (int q = 0; q < 4; ++q) c[i][j][q] = 0.f;

    const int row = tid >> 1, kh = (tid & 1) * 16;
    const int bk = tid >> 3, bn = (tid & 7) * 16;
    const float* pA = A + (size_t)(m0 + row) * 512 + kh;
    const float* pB = B + n0 + bn;

    float4 fa[4], fb[4];
#pragma unroll
    for (int i = 0; i < 4; ++i) {
        fa[i] = *(const float4*)(pA + i * 4);
        fb[i] = *(const float4*)(pB + (size_t)bk * 768 + i * 4);
    }
    {
        uint16_t* a0 = (uint16_t*)sm;
        uint16_t* b0 = (uint16_t*)(sm + 2 * TN_TILE_B);
        stage_tn(a0, a0 + TN_TILE_B / 2, fa, tid);
        stage_nn_b(b0, b0 + NN_BT_B / 2, fb, tid);
    }
    __syncthreads();

    int ib = 0;
    for (int k0 = 0; k0 < 512; k0 += 32, ib ^= 1) {
        const bool has_next = (k0 + 32 < 512);
        if (has_next) {
#pragma unroll
            for (int i = 0; i < 4; ++i) {
                fa[i] = *(const float4*)(pA + k0 + 32 + i * 4);
                fb[i] = *(const float4*)(pB + (size_t)(k0 + 32 + bk) * 768 + i * 4);
            }
        }
        uint16_t* ca = (uint16_t*)(sm + ib * NN_BUF_B);
        uint16_t* cb = (uint16_t*)(sm + ib * NN_BUF_B + 2 * TN_TILE_B);
        compute_chunk<true>(c, ca, ca + TN_TILE_B / 2, cb, cb + NN_BT_B / 2,
                            lane, mrow0, ncol0);
        if (has_next) {
            uint16_t* na = (uint16_t*)(sm + (ib ^ 1) * NN_BUF_B);
            uint16_t* nb = (uint16_t*)(sm + (ib ^ 1) * NN_BUF_B + 2 * TN_TILE_B);
            stage_tn(na, na + TN_TILE_B / 2, fa, tid);
            stage_nn_b(nb, nb + NN_BT_B / 2, fb, tid);
        }
        __syncthreads();
    }
    epilogue_store(c, tmp, nullptr, 256, b * 512 + m0, n0, mrow0, ncol0, lane);
}

// ---------------------------------------------------------------------------
// Attention: tensor-pipe scores + interleaved dual-query exact sparsemax.
// ---------------------------------------------------------------------------
#define SC_STR 522
#define AK_OFF   0
#define AKL_OFF  20480
#define AQ_OFF   40960
#define AQL_OFF  43520
#define ASC_OFF  46080
#define ATTN_SMEM_BYTES (46080 + 32 * SC_STR * 4)   // 112896

__global__ __launch_bounds__(512, 2) void attn_sparsemax_kernel(
    const float* __restrict__ qkv, float* __restrict__ avg)
{
    extern __shared__ __align__(16) char sm[];
    uint16_t* Khi = (uint16_t*)(sm + AK_OFF);
    uint16_t* Klo = (uint16_t*)(sm + AKL_OFF);
    uint16_t* Qhi = (uint16_t*)(sm + AQ_OFF);
    uint16_t* Qlo = (uint16_t*)(sm + AQL_OFF);
    float*    Ssc = (float*)(sm + ASC_OFF);

    const int tid  = threadIdx.x;
    const int lane = tid & 31, w = tid >> 5;
    const int b    = blockIdx.x >> 4;
    const int s0   = (blockIdx.x & 15) << 5;

    const float* qbase = qkv + (size_t)b * 512 * 768;
    const float* kbase = qbase + 256;

    float acc[2][16];
#pragma unroll
    for (int qi = 0; qi < 2; ++qi)
#pragma unroll
        for (int i = 0; i < 16; ++i) acc[qi][i] = 0.f;

    const int lr = lane & 7, lg = lane >> 3;

    for (int h = 0; h < HH; ++h) {
        __syncthreads();

        // ---- stage Q (32 x 32) hi/lo ----
        {
            int r = tid >> 4, e2 = (tid & 15) * 2;
            const float* g = qbase + (size_t)(s0 + r) * 768 + h * 32 + e2;
            uint32_t hp, lp;
            splitpk(g[0], g[1], hp, lp);
            *(uint32_t*)(Qhi + r * AT_STR + e2) = hp;
            *(uint32_t*)(Qlo + r * AT_STR + e2) = lp;
        }

#pragma unroll
        for (int ck = 0; ck < 2; ++ck) {
            if (ck) __syncthreads();
            {
                int r = tid >> 1, kh = (tid & 1) * 16;
                const float* g = kbase + (size_t)(ck * 256 + r) * 768 + h * 32 + kh;
                float4 f[4];
#pragma unroll
                for (int i = 0; i < 4; ++i) f[i] = *(const float4*)(g + i * 4);
                uint4 H0, H1, L0, L1;
                splitpk(f[0].x, f[0].y, H0.x, L0.x); splitpk(f[0].z, f[0].w, H0.y, L0.y);
                splitpk(f[1].x, f[1].y, H0.z, L0.z); splitpk(f[1].z, f[1].w, H0.w, L0.w);
                splitpk(f[2].x, f[2].y, H1.x, L1.x); splitpk(f[2].z, f[2].w, H1.y, L1.y);
                splitpk(f[3].x, f[3].y, H1.z, L1.z); splitpk(f[3].z, f[3].w, H1.w, L1.w);
                *(uint4*)(Khi + r * AT_STR + kh)     = H0;
                *(uint4*)(Khi + r * AT_STR + kh + 8) = H1;
                *(uint4*)(Klo + r * AT_STR + kh)     = L0;
                *(uint4*)(Klo + r * AT_STR + kh + 8) = L1;
            }
            __syncthreads();

            float c[2][2][4];
#pragma unroll
            for (int mi = 0; mi < 2; ++mi)
#pragma unroll
                for (int hf = 0; hf < 2; ++hf)
#pragma unroll
                    for (int q = 0; q < 4; ++q) c[mi][hf][q] = 0.f;

#pragma unroll
            for (int k16 = 0; k16 < 32; k16 += 16) {
                uint32_t aoff = (uint32_t)(((lane & 15) * AT_STR + k16 + ((lane >> 4) << 3)) * 2);
                uint32_t ah[2][4], al[2][4];
#pragma unroll
                for (int mi = 0; mi < 2; ++mi) {
                    ldmx4(ah[mi], cvta_s(Qhi) + aoff + mi * (16 * AT_STR * 2));
                    ldmx4(al[mi], cvta_s(Qlo) + aoff + mi * (16 * AT_STR * 2));
                }
                uint32_t boff = (uint32_t)(((w * 16 + lr + ((lg & 2) << 2)) * AT_STR
                                            + k16 + ((lg & 1) << 3)) * 2);
                uint32_t bh[4], bl[4];
                ldmx4(bh, cvta_s(Khi) + boff);
                ldmx4(bl, cvta_s(Klo) + boff);
#pragma unroll
                for (int mi = 0; mi < 2; ++mi)
#pragma unroll
                    for (int hf = 0; hf < 2; ++hf) {
                        float* cc = c[mi][hf];
                        mma16816(cc, ah[mi], bh[hf * 2], bh[hf * 2 + 1]);
                        mma16816(cc, ah[mi], bl[hf * 2], bl[hf * 2 + 1]);
                        mma16816(cc, al[mi], bh[hf * 2], bh[hf * 2 + 1]);
                    }
            }

#pragma unroll
            for (int mi = 0; mi < 2; ++mi)
#pragma unroll
                for (int hf = 0; hf < 2; ++hf) {
                    int gc = ck * 256 + w * 16 + hf * 8 + ((lane & 3) << 1);
                    int r0 = mi * 16 + (lane >> 2);
                    int r1 = r0 + 8;
                    float v0 = c[mi][hf][0] * 0.17677669529663687f;
                    float v1 = c[mi][hf][1] * 0.17677669529663687f;
                    float v2 = c[mi][hf][2] * 0.17677669529663687f;
                    float v3 = c[mi][hf][3] * 0.17677669529663687f;
                    if (gc     == s0 + r0) v0 = -CUDART_INF_F;
                    if (gc + 1 == s0 + r0) v1 = -CUDART_INF_F;
                    if (gc     == s0 + r1) v2 = -CUDART_INF_F;
                    if (gc + 1 == s0 + r1) v3 = -CUDART_INF_F;
                    *(float2*)&Ssc[r0 * SC_STR + gc] = make_float2(v0, v1);
                    *(float2*)&Ssc[r1 * SC_STR + gc] = make_float2(v2, v3);
                }
        }
        __syncthreads();

        // ---- dual-query exact sparsemax (Michelot), interleaved ----
        float zz0[16], zz1[16];
        {
            int q0 = w * 2, q1 = w * 2 + 1;
#pragma unroll
            for (int i = 0; i < 16; ++i) {
                zz0[i] = Ssc[q0 * SC_STR + lane + 32 * i];
                zz1[i] = Ssc[q1 * SC_STR + lane + 32 * i];
            }
        }
        float tau0 = -CUDART_INF_F, tau1 = -CUDART_INF_F;
        int prev0 = -1, prev1 = -1;
        bool done0 = false, done1 = false;
        for (int it = 0; it < 64; ++it) {
            float sa0 = 0.f, sa1 = 0.f;
            int ca0 = 0, ca1 = 0;
#pragma unroll
            for (int i = 0; i < 16; ++i) {
                if (zz0[i] > tau0) { sa0 += zz0[i]; ca0++; }
                if (zz1[i] > tau1) { sa1 += zz1[i]; ca1++; }
            }
#pragma unroll
            for (int o = 16; o; o >>= 1) {
                sa0 += __shfl_xor_sync(0xffffffffu, sa0, o);
                sa1 += __shfl_xor_sync(0xffffffffu, sa1, o);
            }
            ca0 = __reduce_add_sync(0xffffffffu, ca0);
            ca1 = __reduce_add_sync(0xffffffffu, ca1);
            if (!done0) {
                if (ca0 == prev0 || ca0 == 0) done0 = true;
                else { prev0 = ca0; tau0 = (sa0 - 1.0f) / (float)ca0; }
            }
            if (!done1) {
                if (ca1 == prev1 || ca1 == 0) done1 = true;
                else { prev1 = ca1; tau1 = (sa1 - 1.0f) / (float)ca1; }
            }
            if (done0 && done1) break;
        }
#pragma unroll
        for (int i = 0; i < 16; ++i) {
            acc[0][i] += fmaxf(zz0[i] - tau0, 0.f) * 0.125f;
            acc[1][i] += fmaxf(zz1[i] - tau1, 0.f) * 0.125f;
        }
    }

#pragma unroll
    for (int qi = 0; qi < 2; ++qi) {
        float* dst = avg + (size_t)(b * 512 + s0 + w * 2 + qi) * 512;
#pragma unroll
        for (int i = 0; i < 16; ++i) dst[lane + 32 * i] = acc[qi][i];
    }
}

// ---------------------------------------------------------------------------
extern "C" void kernel_launch(void* const* d_in, const int* in_sizes, int n_in,
                              void* d_out, int out_size)
{
    const float* x  = (const float*)d_in[0];
    const float* Wq = (const float*)d_in[1];
    const float* bq = (const float*)d_in[2];
    const float* Wk = (const float*)d_in[3];
    const float* bk = (const float*)d_in[4];
    const float* Wv = (const float*)d_in[5];
    const float* bv = (const float*)d_in[6];
    const float* Wo = (const float*)d_in[7];
    const float* bo = (const float*)d_in[8];

    float* out = (float*)d_out;                        // [32,512,256]
    float* avg = out + (size_t)NROWS * DD;             // [32,512,512]

    float* qkv = nullptr;
    float* tmp = nullptr;
    cudaGetSymbolAddress((void**)&qkv, g_qkv);
    cudaGetSymbolAddress((void**)&tmp, g_tmp);

    cudaFuncSetAttribute(mma_qkv, cudaFuncAttributeMaxDynamicSharedMemorySize, TN_SMEM_B);
    cudaFuncSetAttribute(mma_out, cudaFuncAttributeMaxDynamicSharedMemorySize, TN_SMEM_B);
    cudaFuncSetAttribute(mma_nn,  cudaFuncAttributeMaxDynamicSharedMemorySize, NN_SMEM_B);
    cudaFuncSetAttribute(attn_sparsemax_kernel,
                         cudaFuncAttributeMaxDynamicSharedMemorySize, ATTN_SMEM_BYTES);

    // 1) QKV projections (HMMA 3xBF16, double-buffered)
    {
        dim3 grid(6, 128);
        mma_qkv<<<grid, 256, TN_SMEM_B>>>(x, Wq, bq, Wk, bk, Wv, bv, qkv);
    }

    // 2) scores (HMMA) + sparsemax + head average -> avg_attention (in d_out)
    attn_sparsemax_kernel<<<NROWS / 32, 512, ATTN_SMEM_BYTES>>>(qkv, avg);

    // 3) tmp[b] = avg[b] @ v[b]  (HMMA, double-buffered)
    {
        dim3 grid(2, 4, BB);
        mma_nn<<<grid, 256, NN_SMEM_B>>>(avg, qkv, tmp);
    }

    // 4) out = tmp @ Wo^T + bo  (HMMA, double-buffered)
    {
        dim3 grid(2, 128);
        mma_out<<<grid, 256, TN_SMEM_B>>>(tmp, Wo, bo, out);
    }
}